// round 12
// baseline (speedup 1.0000x reference)
#include <cuda_runtime.h>
#include <cuda_fp16.h>
#include <math.h>
#include <stdint.h>

// Problem constants
#define BATCH 4
#define TLEN  8192
#define EMB   1024
#define DH    64
#define MF    8
#define NJ    80          // 8 p_q + 8 p_k + 64 v
#define TM    128         // tokens per phase-1 tile (MMA M)
#define KC    32          // K per chunk (2 ks-blocks of 16)
#define NCHUNK (EMB/KC)   // 32
#define NKS   (EMB/16)    // 64 ks-blocks
#define NTILE ((BATCH*TLEN)/TM)   // 256
#define NFEAT (2*MF)
#define INV_SQRT_M 0.35355339059327376f

// ---- device scratch (no allocations allowed) ----
__device__ __half g_WBh[EMB*NJ];          // folded W [e][j] fp16 hi
__device__ __half g_WBl[EMB*NJ];          // fp16 lo residual
__device__ uint4  g_Bfrag[NKS*5*32];      // pre-packed B frags hi: [ks][npair][lane] (160 KB)
__device__ uint4  g_BfragLo[NKS*32];      // lo frags, p-cols only (32 KB)
__device__ float g_bias[NJ];
__device__ float g_qP[BATCH*TLEN*NFEAT];  // finished q features (2 MB)
__device__ float g_Spart[NTILE*NFEAT*DH];
__device__ float g_S[BATCH*NFEAT*DH];

// ---- helpers ----
__device__ __forceinline__ void mma_f16(float* c, const uint32_t* a, uint32_t b0, uint32_t b1) {
    asm volatile("mma.sync.aligned.m16n8k16.row.col.f32.f16.f16.f32 "
        "{%0,%1,%2,%3}, {%4,%5,%6,%7}, {%8,%9}, {%0,%1,%2,%3};"
        : "+f"(c[0]), "+f"(c[1]), "+f"(c[2]), "+f"(c[3])
        : "r"(a[0]), "r"(a[1]), "r"(a[2]), "r"(a[3]), "r"(b0), "r"(b1));
}
// split fp32 pair -> packed fp16 hi + fp16 lo(residual)
__device__ __forceinline__ void split_pack(float vx, float vy, uint32_t& hi, uint32_t& lo) {
    __half2 h = __floats2half2_rn(vx, vy);
    float2 hf = __half22float2(h);
    __half2 l = __floats2half2_rn(vx - hf.x, vy - hf.y);
    hi = *reinterpret_cast<uint32_t*>(&h);
    lo = *reinterpret_cast<uint32_t*>(&l);
}
__device__ __forceinline__ uint32_t packh(__half a, __half b) {   // a -> low, b -> high
    return (uint32_t)__half_as_ushort(a) | ((uint32_t)__half_as_ushort(b) << 16);
}

// ============================================================
// prep: fold Wq@w, Wk@w + Wv into fp16 hi/lo [e][j]; biases.
// ============================================================
__global__ void prep_kernel(const float* __restrict__ w,
                            const float* __restrict__ Wq, const float* __restrict__ bq,
                            const float* __restrict__ Wk, const float* __restrict__ bk,
                            const float* __restrict__ Wv, const float* __restrict__ bv) {
    int g = blockIdx.x * blockDim.x + threadIdx.x;
    if (g < NJ) {
        float bb;
        if (g < MF) {
            bb = 0.f;
            for (int d = 0; d < DH; d++) bb += bq[d] * w[d*MF + g];
        } else if (g < 2*MF) {
            int jj = g - MF;
            bb = 0.f;
            for (int d = 0; d < DH; d++) bb += bk[d] * w[d*MF + jj];
        } else {
            bb = bv[g - 2*MF];
        }
        g_bias[g] = bb;
    }
    if (g >= EMB*NJ) return;
    int e = g / NJ;
    int j = g - e*NJ;
    float val;
    if (j < MF) {
        val = 0.f;
        for (int d = 0; d < DH; d++) val += Wq[e*DH + d] * w[d*MF + j];
    } else if (j < 2*MF) {
        int jj = j - MF;
        val = 0.f;
        for (int d = 0; d < DH; d++) val += Wk[e*DH + d] * w[d*MF + jj];
    } else {
        val = Wv[e*DH + (j - 2*MF)];
    }
    __half h = __float2half_rn(val);
    g_WBh[g] = h;
    g_WBl[g] = __float2half_rn(val - __half2float(h));
}

// ============================================================
// prep2: repack folded W into mma b-fragment layout.
// b-frag (m16n8k16, col B): lane l, n-tile n0 = base + l/4:
//   b0 = {B[k0][n0], B[k0+1][n0]}   k0 = 16*t + 2*(l%4)
//   b1 = {B[k0+8][n0], B[k0+9][n0]}
// uint4 F = (b0,b1) of n-tile 2p | (b0,b1) of n-tile 2p+1
// ============================================================
__global__ void prep2_kernel() {
    int g = blockIdx.x * blockDim.x + threadIdx.x;   // 0..12287
    if (g < NKS*5*32) {
        int l  = g & 31;
        int tp = g >> 5;              // t*5 + p
        int p  = tp % 5;
        int t  = tp / 5;
        int k0 = 16*t + 2*(l & 3);
        int n0 = 16*p + (l >> 2);
        uint4 f;
        f.x = packh(g_WBh[(k0    )*NJ + n0], g_WBh[(k0+1)*NJ + n0]);
        f.y = packh(g_WBh[(k0+8  )*NJ + n0], g_WBh[(k0+9)*NJ + n0]);
        f.z = packh(g_WBh[(k0    )*NJ + n0+8], g_WBh[(k0+1)*NJ + n0+8]);
        f.w = packh(g_WBh[(k0+8  )*NJ + n0+8], g_WBh[(k0+9)*NJ + n0+8]);
        g_Bfrag[tp*32 + l] = f;
    } else if (g < NKS*5*32 + NKS*32) {
        int gg = g - NKS*5*32;
        int l  = gg & 31;
        int t  = gg >> 5;
        int k0 = 16*t + 2*(l & 3);
        int n0 = (l >> 2);            // p = 0 only (cols 0..15)
        uint4 f;
        f.x = packh(g_WBl[(k0    )*NJ + n0], g_WBl[(k0+1)*NJ + n0]);
        f.y = packh(g_WBl[(k0+8  )*NJ + n0], g_WBl[(k0+9)*NJ + n0]);
        f.z = packh(g_WBl[(k0    )*NJ + n0+8], g_WBl[(k0+1)*NJ + n0+8]);
        f.w = packh(g_WBl[(k0+8  )*NJ + n0+8], g_WBl[(k0+9)*NJ + n0+8]);
        g_BfragLo[t*32 + l] = f;
    }
}

// ============================================================
// phase 1: barrier-free HMMA GEMM [128 x 80] — no smem staging.
// A: direct coalesced LDG.64 (fp32 pair) -> fp16 hi/lo frags in regs.
// B: pre-packed fragment tables (L1/L2 resident), 1 LDG.128 each.
// p-cols (0..15): 3-term; v-cols (16..79): 1-term.
// ============================================================
__global__ __launch_bounds__(256, 2) void phase1_kernel(const float* __restrict__ x) {
    __shared__ float res[TM][82];              // 41984 B, epilogue only
    const int tid  = threadIdx.x;
    const int lane = tid & 31;
    const int w    = tid >> 5;                 // warp 0..7 -> rows 16w..16w+15
    const int tile = blockIdx.x;

    // lane-fixed base pointer: row = 16w + lane/4, col = 2*(lane%4)
    const float* xl0 = x + (size_t)(tile * TM + 16 * w + (lane >> 2)) * EMB + 2 * (lane & 3);

    float acc[10][4];
    #pragma unroll
    for (int nt = 0; nt < 10; nt++)
        #pragma unroll
        for (int i = 0; i < 4; i++) acc[nt][i] = 0.f;

    // A prefetch registers: pa[ks*4 + j], j: {(r,c0),(r+8,c0),(r,c0+8),(r+8,c0+8)}
    float2 pa[8];
    #pragma unroll
    for (int ks = 0; ks < 2; ks++) {
        const float* b = xl0 + ks * 16;
        pa[ks*4 + 0] = *reinterpret_cast<const float2*>(b);
        pa[ks*4 + 1] = *reinterpret_cast<const float2*>(b + 8 * EMB);
        pa[ks*4 + 2] = *reinterpret_cast<const float2*>(b + 8);
        pa[ks*4 + 3] = *reinterpret_cast<const float2*>(b + 8 * EMB + 8);
    }

    for (int c = 0; c < NCHUNK; c++) {
        // convert current chunk's A to hi/lo fragments
        uint32_t Ah[2][4], Al[2][4];
        #pragma unroll
        for (int ks = 0; ks < 2; ks++)
            #pragma unroll
            for (int j = 0; j < 4; j++)
                split_pack(pa[ks*4 + j].x, pa[ks*4 + j].y, Ah[ks][j], Al[ks][j]);

        // prefetch next chunk's A (independent of MMAs below)
        if (c + 1 < NCHUNK) {
            const int koff = (c + 1) * KC;
            #pragma unroll
            for (int ks = 0; ks < 2; ks++) {
                const float* b = xl0 + koff + ks * 16;
                pa[ks*4 + 0] = *reinterpret_cast<const float2*>(b);
                pa[ks*4 + 1] = *reinterpret_cast<const float2*>(b + 8 * EMB);
                pa[ks*4 + 2] = *reinterpret_cast<const float2*>(b + 8);
                pa[ks*4 + 3] = *reinterpret_cast<const float2*>(b + 8 * EMB + 8);
            }
        }

        #pragma unroll
        for (int ks = 0; ks < 2; ks++) {
            const int t = 2 * c + ks;
            const uint4* fb = g_Bfrag + (size_t)t * 5 * 32 + lane;
            // p-columns (npair 0): 3-term split
            uint4 F0 = fb[0];
            uint4 FL = g_BfragLo[(size_t)t * 32 + lane];
            mma_f16(acc[0], Ah[ks], F0.x, F0.y);
            mma_f16(acc[1], Ah[ks], F0.z, F0.w);
            mma_f16(acc[0], Ah[ks], FL.x, FL.y);
            mma_f16(acc[1], Ah[ks], FL.z, FL.w);
            mma_f16(acc[0], Al[ks], F0.x, F0.y);
            mma_f16(acc[1], Al[ks], F0.z, F0.w);
            // v-columns (npair 1..4): 1-term
            #pragma unroll
            for (int p = 1; p < 5; p++) {
                uint4 F = fb[p * 32];
                mma_f16(acc[2*p],     Ah[ks], F.x, F.y);
                mma_f16(acc[2*p + 1], Ah[ks], F.z, F.w);
            }
        }
    }

    // ---- epilogue: C frags + bias -> res[tok][82] ----
    {
        int r0 = 16 * w + (lane >> 2);
        #pragma unroll
        for (int nt = 0; nt < 10; nt++) {
            int col = nt * 8 + 2 * (lane & 3);
            float b0 = g_bias[col], b1 = g_bias[col + 1];
            *reinterpret_cast<float2*>(&res[r0][col]) =
                make_float2(acc[nt][0] + b0, acc[nt][1] + b1);
            *reinterpret_cast<float2*>(&res[r0 + 8][col]) =
                make_float2(acc[nt][2] + b0, acc[nt][3] + b1);
        }
    }
    __syncthreads();

    const int t0 = tile * TM;
    // q-path: sincos, store finished qP (cos 0..7 | sin 8..15)
    #pragma unroll
    for (int i = 0; i < 4; i++) {
        int idx = tid + i * 256;                // tok*8 + m
        int tok = idx >> 3;
        int mq  = idx & 7;
        float p = res[tok][mq];
        float sv, cv;
        sincosf(p, &sv, &cv);
        float* qp = g_qP + (size_t)(t0 + tok) * NFEAT;
        qp[mq]      = cv * INV_SQRT_M;
        qp[MF + mq] = sv * INV_SQRT_M;
    }
    __syncthreads();
    // k-path: Kp in place: cos -> 0..7, sin -> 8..15
    #pragma unroll
    for (int i = 0; i < 4; i++) {
        int idx = tid + i * 256;
        int tok = idx >> 3;
        int mm  = idx & 7;
        float p = res[tok][MF + mm];
        float sv, cv;
        sincosf(p, &sv, &cv);
        res[tok][mm]      = cv * INV_SQRT_M;
        res[tok][MF + mm] = sv * INV_SQRT_M;
    }
    __syncthreads();
    // partial S[16][64] for this tile (deterministic per-tile slab)
    const int d  = tid & 63;
    const int fg = tid >> 6;
    float sacc[4] = {0.f, 0.f, 0.f, 0.f};
    for (int tok = 0; tok < TM; tok++) {
        const float* rr = res[tok];
        float v = rr[2 * MF + d];
        #pragma unroll
        for (int ff = 0; ff < 4; ff++)
            sacc[ff] = fmaf(rr[fg * 4 + ff], v, sacc[ff]);
    }
    float* Sp = g_Spart + (size_t)tile * (NFEAT * DH);
    #pragma unroll
    for (int ff = 0; ff < 4; ff++)
        Sp[(fg * 4 + ff) * DH + d] = sacc[ff];
}

// ============================================================
// reduce: S[b][f][d] = sum over 64 tiles (deterministic order)
// ============================================================
__global__ void reduce_kernel() {
    int g  = blockIdx.x * blockDim.x + threadIdx.x;   // 0..4095
    int b  = g >> 10;
    int fd = g & 1023;
    const float* bs = g_Spart + (size_t)b * 64 * (NFEAT * DH) + fd;
    float s = 0.f;
    #pragma unroll
    for (int tt = 0; tt < 64; tt++) s += bs[(size_t)tt * (NFEAT * DH)];
    g_S[g] = s;
}

// ============================================================
// phase 2: y[t][d] = sum_f qP[t][f] * S[b][f][d]
// lane owns a d-pair (S column pair in regs); warp does 16 tokens
// ============================================================
__global__ __launch_bounds__(256) void phase2_kernel(float* __restrict__ y) {
    __shared__ float Ss[NFEAT * DH];    // 4 KB
    __shared__ float qs[128][20];       // 10 KB
    const int tid  = threadIdx.x;
    const int lane = tid & 31;
    const int wp   = tid >> 5;
    const int t0   = blockIdx.x * 128;
    const int b    = t0 / TLEN;

    #pragma unroll
    for (int i = 0; i < 4; i++) Ss[tid + i * 256] = g_S[b * (NFEAT * DH) + tid + i * 256];
    #pragma unroll
    for (int i = 0; i < 2; i++) {
        int idx = tid + i * 256;
        float4 v = *reinterpret_cast<const float4*>(g_qP + (size_t)t0 * NFEAT + idx * 4);
        *reinterpret_cast<float4*>(&qs[idx >> 2][(idx & 3) * 4]) = v;
    }
    __syncthreads();

    float2 Sreg[NFEAT];
    #pragma unroll
    for (int f = 0; f < NFEAT; f++)
        Sreg[f] = *reinterpret_cast<const float2*>(&Ss[f * DH + 2 * lane]);

    #pragma unroll 4
    for (int it = 0; it < 16; it++) {
        int tok = wp * 16 + it;
        const float4* qv = reinterpret_cast<const float4*>(qs[tok]);
        float2 o = make_float2(0.f, 0.f);
        #pragma unroll
        for (int j = 0; j < 4; j++) {
            float4 q4 = qv[j];
            o.x = fmaf(q4.x, Sreg[4*j + 0].x, o.x); o.y = fmaf(q4.x, Sreg[4*j + 0].y, o.y);
            o.x = fmaf(q4.y, Sreg[4*j + 1].x, o.x); o.y = fmaf(q4.y, Sreg[4*j + 1].y, o.y);
            o.x = fmaf(q4.z, Sreg[4*j + 2].x, o.x); o.y = fmaf(q4.z, Sreg[4*j + 2].y, o.y);
            o.x = fmaf(q4.w, Sreg[4*j + 3].x, o.x); o.y = fmaf(q4.w, Sreg[4*j + 3].y, o.y);
        }
        *reinterpret_cast<float2*>(y + (size_t)(t0 + tok) * DH + 2 * lane) = o;
    }
}

// ============================================================
extern "C" void kernel_launch(void* const* d_in, const int* in_sizes, int n_in,
                              void* d_out, int out_size) {
    (void)in_sizes; (void)n_in; (void)out_size;
    const float* x  = (const float*)d_in[0];
    const float* w  = (const float*)d_in[1];
    const float* Wq = (const float*)d_in[2];
    const float* bq = (const float*)d_in[3];
    const float* Wk = (const float*)d_in[4];
    const float* bk = (const float*)d_in[5];
    const float* Wv = (const float*)d_in[6];
    const float* bv = (const float*)d_in[7];
    float* y = (float*)d_out;

    prep_kernel<<<(EMB * NJ + 255) / 256, 256>>>(w, Wq, bq, Wk, bk, Wv, bv);
    prep2_kernel<<<(NKS*5*32 + NKS*32 + 255) / 256, 256>>>();
    phase1_kernel<<<NTILE, 256>>>(x);
    reduce_kernel<<<(BATCH * NFEAT * DH) / 256, 256>>>();
    phase2_kernel<<<(BATCH * TLEN) / 128, 256>>>(y);
}

// round 13
// speedup vs baseline: 1.0497x; 1.0497x over previous
#include <cuda_runtime.h>
#include <cuda_fp16.h>
#include <math.h>
#include <stdint.h>

// Problem constants
#define BATCH 4
#define TLEN  8192
#define EMB   1024
#define DH    64
#define MF    8
#define NJ    80          // 8 p_q + 8 p_k + 64 v
#define TM    128         // tokens per phase-1 tile (MMA M)
#define KC    32          // K per staged chunk
#define NCHUNK (EMB/KC)   // 32
#define NTILE ((BATCH*TLEN)/TM)   // 256
#define NFEAT (2*MF)
#define INV_SQRT_M 0.35355339059327376f

// ---- device scratch (no allocations allowed) ----
__device__ __half g_WBh[EMB*NJ];          // folded W [e][j] fp16 hi (all 80 cols)
__device__ __half g_WBl[EMB*NJ];          // fp16 lo residual (used for cols 0..15)
__device__ float g_bias[NJ];
__device__ float g_qP[BATCH*TLEN*NFEAT];  // finished q features (2 MB)
__device__ float g_Spart[NTILE*NFEAT*DH];
__device__ float g_S[BATCH*NFEAT*DH];

// ---- smem stage layout ----
#define OFF_ALO 10240      // a_hi[128][40] fp16 = 10240 B
#define OFF_BHI 20480      // a_lo same size
#define OFF_BLO 26112      // b_hi[32][88] fp16 = 5632 B
#define STAGE_BYTES 27648  // b_lo[32][24] fp16 = 1536 B
#define DYN_BYTES (2 * STAGE_BYTES)   // 55296; res[128][82] (41984) aliases offset 0

// ---- helpers ----
__device__ __forceinline__ uint32_t smem_u32(const void* p) {
    uint32_t a;
    asm("{ .reg .u64 t; cvta.to.shared.u64 t, %1; cvt.u32.u64 %0, t; }" : "=r"(a) : "l"(p));
    return a;
}
__device__ __forceinline__ void ldsm_x4(uint32_t* r, uint32_t addr) {
    asm volatile("ldmatrix.sync.aligned.m8n8.x4.shared.b16 {%0,%1,%2,%3}, [%4];"
        : "=r"(r[0]), "=r"(r[1]), "=r"(r[2]), "=r"(r[3]) : "r"(addr));
}
__device__ __forceinline__ void ldsm_x4_t(uint32_t* r, uint32_t addr) {
    asm volatile("ldmatrix.sync.aligned.m8n8.x4.trans.shared.b16 {%0,%1,%2,%3}, [%4];"
        : "=r"(r[0]), "=r"(r[1]), "=r"(r[2]), "=r"(r[3]) : "r"(addr));
}
__device__ __forceinline__ void mma_f16(float* c, const uint32_t* a, const uint32_t* b) {
    asm volatile("mma.sync.aligned.m16n8k16.row.col.f32.f16.f16.f32 "
        "{%0,%1,%2,%3}, {%4,%5,%6,%7}, {%8,%9}, {%0,%1,%2,%3};"
        : "+f"(c[0]), "+f"(c[1]), "+f"(c[2]), "+f"(c[3])
        : "r"(a[0]), "r"(a[1]), "r"(a[2]), "r"(a[3]), "r"(b[0]), "r"(b[1]));
}
// split fp32 pair -> packed fp16 hi + fp16 lo(residual)
__device__ __forceinline__ void split_pack(float vx, float vy, uint32_t& hi, uint32_t& lo) {
    __half2 h = __floats2half2_rn(vx, vy);
    float2 hf = __half22float2(h);
    __half2 l = __floats2half2_rn(vx - hf.x, vy - hf.y);
    hi = *reinterpret_cast<uint32_t*>(&h);
    lo = *reinterpret_cast<uint32_t*>(&l);
}

// ============================================================
// prep: fold Wq@w, Wk@w + Wv into fp16 hi/lo [e][j]; biases.
// 4 independent partial sums -> MLP on the fold loop.
// ============================================================
__global__ void prep_kernel(const float* __restrict__ w,
                            const float* __restrict__ Wq, const float* __restrict__ bq,
                            const float* __restrict__ Wk, const float* __restrict__ bk,
                            const float* __restrict__ Wv, const float* __restrict__ bv) {
    int g = blockIdx.x * blockDim.x + threadIdx.x;
    if (g < NJ) {
        float bb;
        if (g < MF) {
            float s0 = 0.f, s1 = 0.f, s2 = 0.f, s3 = 0.f;
            for (int d = 0; d < DH; d += 4) {
                s0 += bq[d]     * w[(d)    *MF + g];
                s1 += bq[d + 1] * w[(d + 1)*MF + g];
                s2 += bq[d + 2] * w[(d + 2)*MF + g];
                s3 += bq[d + 3] * w[(d + 3)*MF + g];
            }
            bb = (s0 + s1) + (s2 + s3);
        } else if (g < 2*MF) {
            int jj = g - MF;
            float s0 = 0.f, s1 = 0.f, s2 = 0.f, s3 = 0.f;
            for (int d = 0; d < DH; d += 4) {
                s0 += bk[d]     * w[(d)    *MF + jj];
                s1 += bk[d + 1] * w[(d + 1)*MF + jj];
                s2 += bk[d + 2] * w[(d + 2)*MF + jj];
                s3 += bk[d + 3] * w[(d + 3)*MF + jj];
            }
            bb = (s0 + s1) + (s2 + s3);
        } else {
            bb = bv[g - 2*MF];
        }
        g_bias[g] = bb;
    }
    if (g >= EMB*NJ) return;
    int e = g / NJ;
    int j = g - e*NJ;
    float val;
    if (j < MF) {
        float s0 = 0.f, s1 = 0.f, s2 = 0.f, s3 = 0.f;
        for (int d = 0; d < DH; d += 4) {
            s0 += Wq[e*DH + d]     * w[(d)    *MF + j];
            s1 += Wq[e*DH + d + 1] * w[(d + 1)*MF + j];
            s2 += Wq[e*DH + d + 2] * w[(d + 2)*MF + j];
            s3 += Wq[e*DH + d + 3] * w[(d + 3)*MF + j];
        }
        val = (s0 + s1) + (s2 + s3);
    } else if (j < 2*MF) {
        int jj = j - MF;
        float s0 = 0.f, s1 = 0.f, s2 = 0.f, s3 = 0.f;
        for (int d = 0; d < DH; d += 4) {
            s0 += Wk[e*DH + d]     * w[(d)    *MF + jj];
            s1 += Wk[e*DH + d + 1] * w[(d + 1)*MF + jj];
            s2 += Wk[e*DH + d + 2] * w[(d + 2)*MF + jj];
            s3 += Wk[e*DH + d + 3] * w[(d + 3)*MF + jj];
        }
        val = (s0 + s1) + (s2 + s3);
    } else {
        val = Wv[e*DH + (j - 2*MF)];
    }
    __half h = __float2half_rn(val);
    g_WBh[g] = h;
    g_WBl[g] = __float2half_rn(val - __half2float(h));
}

// ============================================================
// phase 1: pipelined HMMA fp16 GEMM [128 x 80]  (R11 structure)
//   p-cols (0..15): 3-term split; v-cols (16..79): 1-term hi*hi
// ============================================================
__global__ __launch_bounds__(256, 2) void phase1_kernel(const float* __restrict__ x) {
    extern __shared__ char smc[];
    const int tid  = threadIdx.x;
    const int lane = tid & 31;
    const int w    = tid >> 5;                 // warp 0..7 -> M rows 16w..16w+15
    const int tile = blockIdx.x;
    const float* xrow = x + (size_t)tile * TM * EMB;
    const uint32_t sbase = smem_u32(smc);

    const uint32_t aOffHi = (uint32_t)((16*w + (lane & 15)) * 80 + ((lane >> 4) * 8) * 2);
    const uint32_t bOffHi = (uint32_t)(OFF_BHI + (lane & 15) * 176 + ((lane >> 4) * 8) * 2);
    const uint32_t bOffLo = (uint32_t)(OFF_BLO + (lane & 15) * 48  + ((lane >> 4) * 8) * 2);

    const int sa_tok = tid >> 3;
    const int sa_k4  = (tid & 7) << 2;
    const int sl_k   = tid >> 3;
    const int sl_jp  = tid & 7;

    float acc[10][4];
    #pragma unroll
    for (int nt = 0; nt < 10; nt++)
        #pragma unroll
        for (int i = 0; i < 4; i++) acc[nt][i] = 0.f;

    // ---- prologue: stage chunk 0 into stage 0 ----
    {
        char* sb = smc;
        #pragma unroll
        for (int i = 0; i < 4; i++) {
            int tok = sa_tok + i * 32;
            float4 v = *reinterpret_cast<const float4*>(xrow + (size_t)tok * EMB + sa_k4);
            uint32_t h0, l0, h1, l1;
            split_pack(v.x, v.y, h0, l0);
            split_pack(v.z, v.w, h1, l1);
            uint32_t off = (uint32_t)(tok * 80 + sa_k4 * 2);
            *reinterpret_cast<uint2*>(sb + off)           = make_uint2(h0, h1);
            *reinterpret_cast<uint2*>(sb + OFF_ALO + off) = make_uint2(l0, l1);
        }
        #pragma unroll
        for (int i = 0; i < 5; i++) {
            int idx = tid + i * 256;
            int k  = idx / 40;
            int jp = idx - k * 40;
            *reinterpret_cast<uint32_t*>(sb + OFF_BHI + k * 176 + jp * 4) =
                *reinterpret_cast<const uint32_t*>(&g_WBh[(size_t)k * NJ + 2 * jp]);
        }
        *reinterpret_cast<uint32_t*>(sb + OFF_BLO + sl_k * 48 + sl_jp * 4) =
            *reinterpret_cast<const uint32_t*>(&g_WBl[(size_t)sl_k * NJ + 2 * sl_jp]);
    }
    __syncthreads();

    // ---- pipelined main loop ----
    for (int c = 0; c < NCHUNK; c++) {
        const uint32_t sOff = (uint32_t)((c & 1) * STAGE_BYTES);
        const int nxt = c + 1;

        float4 va[4];
        uint32_t wh[5], wl0;
        if (nxt < NCHUNK) {
            const int ko = nxt * KC;
            #pragma unroll
            for (int i = 0; i < 4; i++) {
                int tok = sa_tok + i * 32;
                va[i] = *reinterpret_cast<const float4*>(xrow + (size_t)tok * EMB + ko + sa_k4);
            }
            #pragma unroll
            for (int i = 0; i < 5; i++) {
                int idx = tid + i * 256;
                int k  = idx / 40;
                int jp = idx - k * 40;
                wh[i] = *reinterpret_cast<const uint32_t*>(&g_WBh[(size_t)(ko + k) * NJ + 2 * jp]);
            }
            wl0 = *reinterpret_cast<const uint32_t*>(&g_WBl[(size_t)(ko + sl_k) * NJ + 2 * sl_jp]);
        }

        const uint32_t aHiAddr = sbase + sOff + aOffHi;
        const uint32_t aLoAddr = aHiAddr + OFF_ALO;
        const uint32_t bHiAddr = sbase + sOff + bOffHi;
        const uint32_t bLoAddr = sbase + sOff + bOffLo;
        #pragma unroll
        for (int ks = 0; ks < 2; ks++) {
            uint32_t Ah[4], Al[4];
            ldsm_x4(Ah, aHiAddr + ks * 32);
            ldsm_x4(Al, aLoAddr + ks * 32);
            // np = 0 : p-columns 0..15, 3-term split
            {
                uint32_t Bh[4], Bl[4];
                ldsm_x4_t(Bh, bHiAddr + ks * 2816);
                ldsm_x4_t(Bl, bLoAddr + ks * 768);
                mma_f16(acc[0], Ah, Bh + 0);
                mma_f16(acc[1], Ah, Bh + 2);
                mma_f16(acc[0], Ah, Bl + 0);
                mma_f16(acc[1], Ah, Bl + 2);
                mma_f16(acc[0], Al, Bh + 0);
                mma_f16(acc[1], Al, Bh + 2);
            }
            // np = 1..4 : v-columns, 1-term hi*hi
            #pragma unroll
            for (int np = 1; np < 5; np++) {
                uint32_t Bh[4];
                ldsm_x4_t(Bh, bHiAddr + ks * 2816 + np * 32);
                mma_f16(acc[2*np],     Ah, Bh + 0);
                mma_f16(acc[2*np + 1], Ah, Bh + 2);
            }
        }

        if (nxt < NCHUNK) {
            char* sb = smc + (nxt & 1) * STAGE_BYTES;
            #pragma unroll
            for (int i = 0; i < 4; i++) {
                int tok = sa_tok + i * 32;
                uint32_t h0, l0, h1, l1;
                split_pack(va[i].x, va[i].y, h0, l0);
                split_pack(va[i].z, va[i].w, h1, l1);
                uint32_t off = (uint32_t)(tok * 80 + sa_k4 * 2);
                *reinterpret_cast<uint2*>(sb + off)           = make_uint2(h0, h1);
                *reinterpret_cast<uint2*>(sb + OFF_ALO + off) = make_uint2(l0, l1);
            }
            #pragma unroll
            for (int i = 0; i < 5; i++) {
                int idx = tid + i * 256;
                int k  = idx / 40;
                int jp = idx - k * 40;
                *reinterpret_cast<uint32_t*>(sb + OFF_BHI + k * 176 + jp * 4) = wh[i];
            }
            *reinterpret_cast<uint32_t*>(sb + OFF_BLO + sl_k * 48 + sl_jp * 4) = wl0;
        }
        __syncthreads();
    }

    // ---- epilogue: C frags + bias -> res[tok][82] (aliases stage smem) ----
    float (*res)[82] = reinterpret_cast<float (*)[82]>(smc);
    {
        int r0 = 16 * w + (lane >> 2);
        #pragma unroll
        for (int nt = 0; nt < 10; nt++) {
            int col = nt * 8 + 2 * (lane & 3);
            float b0 = g_bias[col], b1 = g_bias[col + 1];
            *reinterpret_cast<float2*>(&res[r0][col]) =
                make_float2(acc[nt][0] + b0, acc[nt][1] + b1);
            *reinterpret_cast<float2*>(&res[r0 + 8][col]) =
                make_float2(acc[nt][2] + b0, acc[nt][3] + b1);
        }
    }
    __syncthreads();

    const int t0 = tile * TM;
    // q-path: sincos, store finished qP (cos 0..7 | sin 8..15)
    #pragma unroll
    for (int i = 0; i < 4; i++) {
        int idx = tid + i * 256;                // tok*8 + m
        int tok = idx >> 3;
        int mq  = idx & 7;
        float p = res[tok][mq];
        float sv, cv;
        sincosf(p, &sv, &cv);
        float* qp = g_qP + (size_t)(t0 + tok) * NFEAT;
        qp[mq]      = cv * INV_SQRT_M;
        qp[MF + mq] = sv * INV_SQRT_M;
    }
    __syncthreads();
    // k-path: Kp in place: cos -> 0..7, sin -> 8..15
    #pragma unroll
    for (int i = 0; i < 4; i++) {
        int idx = tid + i * 256;
        int tok = idx >> 3;
        int mm  = idx & 7;
        float p = res[tok][MF + mm];
        float sv, cv;
        sincosf(p, &sv, &cv);
        res[tok][mm]      = cv * INV_SQRT_M;
        res[tok][MF + mm] = sv * INV_SQRT_M;
    }
    __syncthreads();
    // partial S[16][64] for this tile (deterministic per-tile slab)
    const int d  = tid & 63;
    const int fg = tid >> 6;
    float sacc[4] = {0.f, 0.f, 0.f, 0.f};
    for (int tok = 0; tok < TM; tok++) {
        const float* rr = res[tok];
        float v = rr[2 * MF + d];
        #pragma unroll
        for (int ff = 0; ff < 4; ff++)
            sacc[ff] = fmaf(rr[fg * 4 + ff], v, sacc[ff]);
    }
    float* Sp = g_Spart + (size_t)tile * (NFEAT * DH);
    #pragma unroll
    for (int ff = 0; ff < 4; ff++)
        Sp[(fg * 4 + ff) * DH + d] = sacc[ff];
}

// ============================================================
// reduce: S[b][f][d] = sum over 64 tiles. 4 threads per (b,fd),
// 16 tiles each, fixed-order smem combine (deterministic).
// grid 64 x 256 threads -> fills the chip.
// ============================================================
__global__ __launch_bounds__(256) void reduce_kernel() {
    __shared__ float partial[4][64];
    const int tid = threadIdx.x;
    const int fdl  = tid & 63;                 // 0..63 (coalesced)
    const int part = tid >> 6;                 // 0..3 -> tiles part*16..+15
    const int b      = blockIdx.x >> 4;        // 4 batches x 16 fd-groups
    const int fdbase = (blockIdx.x & 15) * 64;
    const int fd     = fdbase + fdl;

    const float* bs = g_Spart + (size_t)b * 64 * (NFEAT * DH) + fd;
    float s = 0.f;
    #pragma unroll
    for (int tt = 0; tt < 16; tt++)
        s += bs[(size_t)(part * 16 + tt) * (NFEAT * DH)];
    partial[part][fdl] = s;
    __syncthreads();
    if (part == 0) {
        float r = ((partial[0][fdl] + partial[1][fdl]) +
                   (partial[2][fdl] + partial[3][fdl]));
        g_S[b * (NFEAT * DH) + fd] = r;
    }
}

// ============================================================
// phase 2: y[t][d] = sum_f qP[t][f] * S[b][f][d]
// 64 tokens/block -> grid 512 for occupancy; lane owns a d-pair.
// ============================================================
__global__ __launch_bounds__(256) void phase2_kernel(float* __restrict__ y) {
    __shared__ float Ss[NFEAT * DH];    // 4 KB
    __shared__ float qs[64][20];        // 5 KB
    const int tid  = threadIdx.x;
    const int lane = tid & 31;
    const int wp   = tid >> 5;
    const int t0   = blockIdx.x * 64;
    const int b    = t0 / TLEN;

    #pragma unroll
    for (int i = 0; i < 4; i++) Ss[tid + i * 256] = g_S[b * (NFEAT * DH) + tid + i * 256];
    {
        int idx = tid;                  // 256 float4s = 64 tokens x 16 feats
        float4 v = *reinterpret_cast<const float4*>(g_qP + (size_t)t0 * NFEAT + idx * 4);
        *reinterpret_cast<float4*>(&qs[idx >> 2][(idx & 3) * 4]) = v;
    }
    __syncthreads();

    float2 Sreg[NFEAT];
    #pragma unroll
    for (int f = 0; f < NFEAT; f++)
        Sreg[f] = *reinterpret_cast<const float2*>(&Ss[f * DH + 2 * lane]);

    #pragma unroll
    for (int it = 0; it < 8; it++) {
        int tok = wp * 8 + it;
        const float4* qv = reinterpret_cast<const float4*>(qs[tok]);
        float2 o = make_float2(0.f, 0.f);
        #pragma unroll
        for (int j = 0; j < 4; j++) {
            float4 q4 = qv[j];
            o.x = fmaf(q4.x, Sreg[4*j + 0].x, o.x); o.y = fmaf(q4.x, Sreg[4*j + 0].y, o.y);
            o.x = fmaf(q4.y, Sreg[4*j + 1].x, o.x); o.y = fmaf(q4.y, Sreg[4*j + 1].y, o.y);
            o.x = fmaf(q4.z, Sreg[4*j + 2].x, o.x); o.y = fmaf(q4.z, Sreg[4*j + 2].y, o.y);
            o.x = fmaf(q4.w, Sreg[4*j + 3].x, o.x); o.y = fmaf(q4.w, Sreg[4*j + 3].y, o.y);
        }
        *reinterpret_cast<float2*>(y + (size_t)(t0 + tok) * DH + 2 * lane) = o;
    }
}

// ============================================================
extern "C" void kernel_launch(void* const* d_in, const int* in_sizes, int n_in,
                              void* d_out, int out_size) {
    (void)in_sizes; (void)n_in; (void)out_size;
    const float* x  = (const float*)d_in[0];
    const float* w  = (const float*)d_in[1];
    const float* Wq = (const float*)d_in[2];
    const float* bq = (const float*)d_in[3];
    const float* Wk = (const float*)d_in[4];
    const float* bk = (const float*)d_in[5];
    const float* Wv = (const float*)d_in[6];
    const float* bv = (const float*)d_in[7];
    float* y = (float*)d_out;

    static int attr_set = 0;
    if (!attr_set) {
        cudaFuncSetAttribute(phase1_kernel, cudaFuncAttributeMaxDynamicSharedMemorySize, DYN_BYTES);
        attr_set = 1;
    }

    prep_kernel<<<(EMB * NJ + 255) / 256, 256>>>(w, Wq, bq, Wk, bk, Wv, bv);
    phase1_kernel<<<NTILE, 256, DYN_BYTES>>>(x);
    reduce_kernel<<<64, 256>>>();
    phase2_kernel<<<(BATCH * TLEN) / 64, 256>>>(y);
}

// round 14
// speedup vs baseline: 1.0745x; 1.0237x over previous
#include <cuda_runtime.h>
#include <cuda_fp16.h>
#include <math.h>
#include <stdint.h>

// Problem constants
#define BATCH 4
#define TLEN  8192
#define EMB   1024
#define DH    64
#define MF    8
#define NJ    80          // 8 p_q + 8 p_k + 64 v
#define TM    128         // tokens per phase-1 tile (MMA M)
#define KC    32          // K per staged chunk
#define NCHUNK (EMB/KC)   // 32
#define NTILE ((BATCH*TLEN)/TM)   // 256
#define NFEAT (2*MF)
#define INV_SQRT_M 0.35355339059327376f

// ---- device scratch (no allocations allowed) ----
__device__ __half g_WBh[EMB*NJ];          // folded W [e][j] fp16 hi (all 80 cols)
__device__ __half g_WBl[EMB*NJ];          // fp16 lo residual (used for cols 0..15)
__device__ float g_bias[NJ];
__device__ float g_qP[BATCH*TLEN*NFEAT];  // finished q features (2 MB)
__device__ float g_Spart[NTILE*NFEAT*DH];
__device__ float g_S[BATCH*NFEAT*DH];

// ---- smem stage layout (main loop) ----
#define OFF_ALO 10240
#define OFF_BHI 20480
#define OFF_BLO 26112
#define STAGE_BYTES 27648
#define DYN_BYTES (2 * STAGE_BYTES)   // 55296

// ---- epilogue panel layout (aliases stage smem after final sync) ----
#define P_KPH 0            // Kp hi [128][24] half, 48 B rows  (6144 B)
#define P_KPL 6144         // Kp lo
#define P_VH  12288        // V hi  [128][72] half, 144 B rows (18432 B)
#define P_VL  30720        // V lo  (ends 49152 < 55296)
// Sred [8][1024] float at offset 0 (32768 B), used after post-MMA syncthreads

// ---- helpers ----
__device__ __forceinline__ uint32_t smem_u32(const void* p) {
    uint32_t a;
    asm("{ .reg .u64 t; cvta.to.shared.u64 t, %1; cvt.u32.u64 %0, t; }" : "=r"(a) : "l"(p));
    return a;
}
__device__ __forceinline__ void ldsm_x4(uint32_t* r, uint32_t addr) {
    asm volatile("ldmatrix.sync.aligned.m8n8.x4.shared.b16 {%0,%1,%2,%3}, [%4];"
        : "=r"(r[0]), "=r"(r[1]), "=r"(r[2]), "=r"(r[3]) : "r"(addr));
}
__device__ __forceinline__ void ldsm_x4_t(uint32_t* r, uint32_t addr) {
    asm volatile("ldmatrix.sync.aligned.m8n8.x4.trans.shared.b16 {%0,%1,%2,%3}, [%4];"
        : "=r"(r[0]), "=r"(r[1]), "=r"(r[2]), "=r"(r[3]) : "r"(addr));
}
__device__ __forceinline__ void mma_f16(float* c, const uint32_t* a, const uint32_t* b) {
    asm volatile("mma.sync.aligned.m16n8k16.row.col.f32.f16.f16.f32 "
        "{%0,%1,%2,%3}, {%4,%5,%6,%7}, {%8,%9}, {%0,%1,%2,%3};"
        : "+f"(c[0]), "+f"(c[1]), "+f"(c[2]), "+f"(c[3])
        : "r"(a[0]), "r"(a[1]), "r"(a[2]), "r"(a[3]), "r"(b[0]), "r"(b[1]));
}
// split fp32 pair -> packed fp16 hi + fp16 lo(residual)
__device__ __forceinline__ void split_pack(float vx, float vy, uint32_t& hi, uint32_t& lo) {
    __half2 h = __floats2half2_rn(vx, vy);
    float2 hf = __half22float2(h);
    __half2 l = __floats2half2_rn(vx - hf.x, vy - hf.y);
    hi = *reinterpret_cast<uint32_t*>(&h);
    lo = *reinterpret_cast<uint32_t*>(&l);
}

// ============================================================
// prep: fold Wq@w, Wk@w + Wv into fp16 hi/lo [e][j]; biases.
// ============================================================
__global__ void prep_kernel(const float* __restrict__ w,
                            const float* __restrict__ Wq, const float* __restrict__ bq,
                            const float* __restrict__ Wk, const float* __restrict__ bk,
                            const float* __restrict__ Wv, const float* __restrict__ bv) {
    int g = blockIdx.x * blockDim.x + threadIdx.x;
    if (g < NJ) {
        float bb;
        if (g < MF) {
            float s0 = 0.f, s1 = 0.f, s2 = 0.f, s3 = 0.f;
            for (int d = 0; d < DH; d += 4) {
                s0 += bq[d]     * w[(d)    *MF + g];
                s1 += bq[d + 1] * w[(d + 1)*MF + g];
                s2 += bq[d + 2] * w[(d + 2)*MF + g];
                s3 += bq[d + 3] * w[(d + 3)*MF + g];
            }
            bb = (s0 + s1) + (s2 + s3);
        } else if (g < 2*MF) {
            int jj = g - MF;
            float s0 = 0.f, s1 = 0.f, s2 = 0.f, s3 = 0.f;
            for (int d = 0; d < DH; d += 4) {
                s0 += bk[d]     * w[(d)    *MF + jj];
                s1 += bk[d + 1] * w[(d + 1)*MF + jj];
                s2 += bk[d + 2] * w[(d + 2)*MF + jj];
                s3 += bk[d + 3] * w[(d + 3)*MF + jj];
            }
            bb = (s0 + s1) + (s2 + s3);
        } else {
            bb = bv[g - 2*MF];
        }
        g_bias[g] = bb;
    }
    if (g >= EMB*NJ) return;
    int e = g / NJ;
    int j = g - e*NJ;
    float val;
    if (j < MF) {
        float s0 = 0.f, s1 = 0.f, s2 = 0.f, s3 = 0.f;
        for (int d = 0; d < DH; d += 4) {
            s0 += Wq[e*DH + d]     * w[(d)    *MF + j];
            s1 += Wq[e*DH + d + 1] * w[(d + 1)*MF + j];
            s2 += Wq[e*DH + d + 2] * w[(d + 2)*MF + j];
            s3 += Wq[e*DH + d + 3] * w[(d + 3)*MF + j];
        }
        val = (s0 + s1) + (s2 + s3);
    } else if (j < 2*MF) {
        int jj = j - MF;
        float s0 = 0.f, s1 = 0.f, s2 = 0.f, s3 = 0.f;
        for (int d = 0; d < DH; d += 4) {
            s0 += Wk[e*DH + d]     * w[(d)    *MF + jj];
            s1 += Wk[e*DH + d + 1] * w[(d + 1)*MF + jj];
            s2 += Wk[e*DH + d + 2] * w[(d + 2)*MF + jj];
            s3 += Wk[e*DH + d + 3] * w[(d + 3)*MF + jj];
        }
        val = (s0 + s1) + (s2 + s3);
    } else {
        val = Wv[e*DH + (j - 2*MF)];
    }
    __half h = __float2half_rn(val);
    g_WBh[g] = h;
    g_WBl[g] = __float2half_rn(val - __half2float(h));
}

// ============================================================
// phase 1: pipelined HMMA fp16 GEMM [128 x 80] + MMA-based epilogue
// ============================================================
__global__ __launch_bounds__(256, 2) void phase1_kernel(const float* __restrict__ x) {
    extern __shared__ char smc[];
    const int tid  = threadIdx.x;
    const int lane = tid & 31;
    const int w    = tid >> 5;
    const int tile = blockIdx.x;
    const float* xrow = x + (size_t)tile * TM * EMB;
    const uint32_t sbase = smem_u32(smc);

    const uint32_t aOffHi = (uint32_t)((16*w + (lane & 15)) * 80 + ((lane >> 4) * 8) * 2);
    const uint32_t bOffHi = (uint32_t)(OFF_BHI + (lane & 15) * 176 + ((lane >> 4) * 8) * 2);
    const uint32_t bOffLo = (uint32_t)(OFF_BLO + (lane & 15) * 48  + ((lane >> 4) * 8) * 2);

    const int sa_tok = tid >> 3;
    const int sa_k4  = (tid & 7) << 2;
    const int sl_k   = tid >> 3;
    const int sl_jp  = tid & 7;

    float acc[10][4];
    #pragma unroll
    for (int nt = 0; nt < 10; nt++)
        #pragma unroll
        for (int i = 0; i < 4; i++) acc[nt][i] = 0.f;

    // ---- prologue: stage chunk 0 into stage 0 ----
    {
        char* sb = smc;
        #pragma unroll
        for (int i = 0; i < 4; i++) {
            int tok = sa_tok + i * 32;
            float4 v = *reinterpret_cast<const float4*>(xrow + (size_t)tok * EMB + sa_k4);
            uint32_t h0, l0, h1, l1;
            split_pack(v.x, v.y, h0, l0);
            split_pack(v.z, v.w, h1, l1);
            uint32_t off = (uint32_t)(tok * 80 + sa_k4 * 2);
            *reinterpret_cast<uint2*>(sb + off)           = make_uint2(h0, h1);
            *reinterpret_cast<uint2*>(sb + OFF_ALO + off) = make_uint2(l0, l1);
        }
        #pragma unroll
        for (int i = 0; i < 5; i++) {
            int idx = tid + i * 256;
            int k  = idx / 40;
            int jp = idx - k * 40;
            *reinterpret_cast<uint32_t*>(sb + OFF_BHI + k * 176 + jp * 4) =
                *reinterpret_cast<const uint32_t*>(&g_WBh[(size_t)k * NJ + 2 * jp]);
        }
        *reinterpret_cast<uint32_t*>(sb + OFF_BLO + sl_k * 48 + sl_jp * 4) =
            *reinterpret_cast<const uint32_t*>(&g_WBl[(size_t)sl_k * NJ + 2 * sl_jp]);
    }
    __syncthreads();

    // ---- pipelined main loop ----
    for (int c = 0; c < NCHUNK; c++) {
        const uint32_t sOff = (uint32_t)((c & 1) * STAGE_BYTES);
        const int nxt = c + 1;

        float4 va[4];
        uint32_t wh[5], wl0;
        if (nxt < NCHUNK) {
            const int ko = nxt * KC;
            #pragma unroll
            for (int i = 0; i < 4; i++) {
                int tok = sa_tok + i * 32;
                va[i] = *reinterpret_cast<const float4*>(xrow + (size_t)tok * EMB + ko + sa_k4);
            }
            #pragma unroll
            for (int i = 0; i < 5; i++) {
                int idx = tid + i * 256;
                int k  = idx / 40;
                int jp = idx - k * 40;
                wh[i] = *reinterpret_cast<const uint32_t*>(&g_WBh[(size_t)(ko + k) * NJ + 2 * jp]);
            }
            wl0 = *reinterpret_cast<const uint32_t*>(&g_WBl[(size_t)(ko + sl_k) * NJ + 2 * sl_jp]);
        }

        const uint32_t aHiAddr = sbase + sOff + aOffHi;
        const uint32_t aLoAddr = aHiAddr + OFF_ALO;
        const uint32_t bHiAddr = sbase + sOff + bOffHi;
        const uint32_t bLoAddr = sbase + sOff + bOffLo;
        #pragma unroll
        for (int ks = 0; ks < 2; ks++) {
            uint32_t Ah[4], Al[4];
            ldsm_x4(Ah, aHiAddr + ks * 32);
            ldsm_x4(Al, aLoAddr + ks * 32);
            {
                uint32_t Bh[4], Bl[4];
                ldsm_x4_t(Bh, bHiAddr + ks * 2816);
                ldsm_x4_t(Bl, bLoAddr + ks * 768);
                mma_f16(acc[0], Ah, Bh + 0);
                mma_f16(acc[1], Ah, Bh + 2);
                mma_f16(acc[0], Ah, Bl + 0);
                mma_f16(acc[1], Ah, Bl + 2);
                mma_f16(acc[0], Al, Bh + 0);
                mma_f16(acc[1], Al, Bh + 2);
            }
            #pragma unroll
            for (int np = 1; np < 5; np++) {
                uint32_t Bh[4];
                ldsm_x4_t(Bh, bHiAddr + ks * 2816 + np * 32);
                mma_f16(acc[2*np],     Ah, Bh + 0);
                mma_f16(acc[2*np + 1], Ah, Bh + 2);
            }
        }

        if (nxt < NCHUNK) {
            char* sb = smc + (nxt & 1) * STAGE_BYTES;
            #pragma unroll
            for (int i = 0; i < 4; i++) {
                int tok = sa_tok + i * 32;
                uint32_t h0, l0, h1, l1;
                split_pack(va[i].x, va[i].y, h0, l0);
                split_pack(va[i].z, va[i].w, h1, l1);
                uint32_t off = (uint32_t)(tok * 80 + sa_k4 * 2);
                *reinterpret_cast<uint2*>(sb + off)           = make_uint2(h0, h1);
                *reinterpret_cast<uint2*>(sb + OFF_ALO + off) = make_uint2(l0, l1);
            }
            #pragma unroll
            for (int i = 0; i < 5; i++) {
                int idx = tid + i * 256;
                int k  = idx / 40;
                int jp = idx - k * 40;
                *reinterpret_cast<uint32_t*>(sb + OFF_BHI + k * 176 + jp * 4) = wh[i];
            }
            *reinterpret_cast<uint32_t*>(sb + OFF_BLO + sl_k * 48 + sl_jp * 4) = wl0;
        }
        __syncthreads();   // final iteration: all compute done -> panels safe
    }

    // ================= MMA-based epilogue =================
    const int t0 = tile * TM;
    const int r0 = 16 * w + (lane >> 2);
    const int cq = 2 * (lane & 3);

    // q-path: acc[0] + bias -> sincos -> g_qP (register direct)
    {
        float2 b2 = *reinterpret_cast<const float2*>(&g_bias[cq]);
        float sv0, cv0, sv1, cv1;
        sincosf(acc[0][0] + b2.x, &sv0, &cv0);
        sincosf(acc[0][1] + b2.y, &sv1, &cv1);
        float* qp = g_qP + (size_t)(t0 + r0) * NFEAT;
        *reinterpret_cast<float2*>(qp + cq)      = make_float2(cv0*INV_SQRT_M, cv1*INV_SQRT_M);
        *reinterpret_cast<float2*>(qp + MF + cq) = make_float2(sv0*INV_SQRT_M, sv1*INV_SQRT_M);
        sincosf(acc[0][2] + b2.x, &sv0, &cv0);
        sincosf(acc[0][3] + b2.y, &sv1, &cv1);
        qp = g_qP + (size_t)(t0 + r0 + 8) * NFEAT;
        *reinterpret_cast<float2*>(qp + cq)      = make_float2(cv0*INV_SQRT_M, cv1*INV_SQRT_M);
        *reinterpret_cast<float2*>(qp + MF + cq) = make_float2(sv0*INV_SQRT_M, sv1*INV_SQRT_M);
    }
    // k-path: acc[1] + bias -> sincos -> Kp hi/lo panels (fp16)
    {
        float2 b2 = *reinterpret_cast<const float2*>(&g_bias[8 + cq]);
        #pragma unroll
        for (int half = 0; half < 2; half++) {
            int row = r0 + half * 8;
            float sv0, cv0, sv1, cv1;
            sincosf(acc[1][2*half + 0] + b2.x, &sv0, &cv0);
            sincosf(acc[1][2*half + 1] + b2.y, &sv1, &cv1);
            uint32_t hi, lo;
            split_pack(cv0*INV_SQRT_M, cv1*INV_SQRT_M, hi, lo);
            *reinterpret_cast<uint32_t*>(smc + P_KPH + row*48 + 2*cq) = hi;
            *reinterpret_cast<uint32_t*>(smc + P_KPL + row*48 + 2*cq) = lo;
            split_pack(sv0*INV_SQRT_M, sv1*INV_SQRT_M, hi, lo);
            *reinterpret_cast<uint32_t*>(smc + P_KPH + row*48 + 16 + 2*cq) = hi;
            *reinterpret_cast<uint32_t*>(smc + P_KPL + row*48 + 16 + 2*cq) = lo;
        }
    }
    // v: acc[2..9] + bias -> V hi/lo panels (fp16)
    #pragma unroll
    for (int nt = 2; nt < 10; nt++) {
        int dcol = (nt - 2) * 8 + cq;
        float2 b2 = *reinterpret_cast<const float2*>(&g_bias[nt*8 + cq]);
        uint32_t hi, lo;
        split_pack(acc[nt][0] + b2.x, acc[nt][1] + b2.y, hi, lo);
        *reinterpret_cast<uint32_t*>(smc + P_VH + r0*144 + 2*dcol) = hi;
        *reinterpret_cast<uint32_t*>(smc + P_VL + r0*144 + 2*dcol) = lo;
        split_pack(acc[nt][2] + b2.x, acc[nt][3] + b2.y, hi, lo);
        *reinterpret_cast<uint32_t*>(smc + P_VH + (r0+8)*144 + 2*dcol) = hi;
        *reinterpret_cast<uint32_t*>(smc + P_VL + (r0+8)*144 + 2*dcol) = lo;
    }
    __syncwarp();

    // ldsm: A = Kp^T (feat x token) via trans-ldsm of Kp[tok][f]
    uint32_t Akh[4], Akl[4];
    {
        uint32_t aoff = (uint32_t)((16*w + (lane & 7) + ((lane & 16) >> 1)) * 48 + (lane & 8) * 2);
        ldsm_x4_t(Akh, sbase + P_KPH + aoff);
        ldsm_x4_t(Akl, sbase + P_KPL + aoff);
    }
    // B = V (token x d), 4 trans-ldsm cover n=64
    uint32_t Vh4[4][4], Vl4[4][4];
    {
        uint32_t boff = (uint32_t)((16*w + (lane & 15)) * 144 + ((lane >> 4) * 8) * 2);
        #pragma unroll
        for (int g2 = 0; g2 < 4; g2++) {
            ldsm_x4_t(Vh4[g2], sbase + P_VH + boff + g2 * 32);
            ldsm_x4_t(Vl4[g2], sbase + P_VL + boff + g2 * 32);
        }
    }
    // S-partial: 3-term split MMA (Kh*Vh + Kh*Vl + Kl*Vh)
    float cs[8][4];
    #pragma unroll
    for (int nt = 0; nt < 8; nt++)
        #pragma unroll
        for (int i = 0; i < 4; i++) cs[nt][i] = 0.f;
    #pragma unroll
    for (int nt = 0; nt < 8; nt++) {
        int g2 = nt >> 1, sel = (nt & 1) * 2;
        mma_f16(cs[nt], Akh, &Vh4[g2][sel]);
        mma_f16(cs[nt], Akh, &Vl4[g2][sel]);
        mma_f16(cs[nt], Akl, &Vh4[g2][sel]);
    }
    __syncthreads();   // all panel reads done -> Sred may alias

    // per-warp partial S -> Sred[w][16][64], fixed-order combine
    float* Sred = reinterpret_cast<float*>(smc);
    {
        int f0 = lane >> 2;
        #pragma unroll
        for (int nt = 0; nt < 8; nt++) {
            int dd = nt * 8 + cq;
            *reinterpret_cast<float2*>(&Sred[w*1024 + f0*64 + dd])     = make_float2(cs[nt][0], cs[nt][1]);
            *reinterpret_cast<float2*>(&Sred[w*1024 + (f0+8)*64 + dd]) = make_float2(cs[nt][2], cs[nt][3]);
        }
    }
    __syncthreads();
    #pragma unroll
    for (int i = 0; i < 4; i++) {
        int slot = tid + i * 256;
        float s = 0.f;
        #pragma unroll
        for (int ww = 0; ww < 8; ww++) s += Sred[ww*1024 + slot];
        g_Spart[(size_t)tile * (NFEAT*DH) + slot] = s;
    }
}

// ============================================================
// reduce: S[b][f][d] = sum over 64 tiles. 4 threads per (b,fd).
// ============================================================
__global__ __launch_bounds__(256) void reduce_kernel() {
    __shared__ float partial[4][64];
    const int tid = threadIdx.x;
    const int fdl  = tid & 63;
    const int part = tid >> 6;
    const int b      = blockIdx.x >> 4;
    const int fdbase = (blockIdx.x & 15) * 64;
    const int fd     = fdbase + fdl;

    const float* bs = g_Spart + (size_t)b * 64 * (NFEAT * DH) + fd;
    float s = 0.f;
    #pragma unroll
    for (int tt = 0; tt < 16; tt++)
        s += bs[(size_t)(part * 16 + tt) * (NFEAT * DH)];
    partial[part][fdl] = s;
    __syncthreads();
    if (part == 0) {
        float r = ((partial[0][fdl] + partial[1][fdl]) +
                   (partial[2][fdl] + partial[3][fdl]));
        g_S[b * (NFEAT * DH) + fd] = r;
    }
}

// ============================================================
// phase 2: y[t][d] = sum_f qP[t][f] * S[b][f][d]
// 128 threads / 32 tokens per block -> grid 1024
// ============================================================
__global__ __launch_bounds__(128) void phase2_kernel(float* __restrict__ y) {
    __shared__ float Ss[NFEAT * DH];    // 4 KB
    __shared__ float qs[32][20];        // 2.5 KB
    const int tid  = threadIdx.x;
    const int lane = tid & 31;
    const int wp   = tid >> 5;
    const int t0   = blockIdx.x * 32;
    const int b    = t0 / TLEN;

    #pragma unroll
    for (int i = 0; i < 8; i++) Ss[tid + i * 128] = g_S[b * (NFEAT * DH) + tid + i * 128];
    {
        int idx = tid;                  // 128 float4s = 32 tokens x 16 feats
        float4 v = *reinterpret_cast<const float4*>(g_qP + (size_t)t0 * NFEAT + idx * 4);
        *reinterpret_cast<float4*>(&qs[idx >> 2][(idx & 3) * 4]) = v;
    }
    __syncthreads();

    float2 Sreg[NFEAT];
    #pragma unroll
    for (int f = 0; f < NFEAT; f++)
        Sreg[f] = *reinterpret_cast<const float2*>(&Ss[f * DH + 2 * lane]);

    #pragma unroll
    for (int it = 0; it < 8; it++) {
        int tok = wp * 8 + it;
        const float4* qv = reinterpret_cast<const float4*>(qs[tok]);
        float2 o = make_float2(0.f, 0.f);
        #pragma unroll
        for (int j = 0; j < 4; j++) {
            float4 q4 = qv[j];
            o.x = fmaf(q4.x, Sreg[4*j + 0].x, o.x); o.y = fmaf(q4.x, Sreg[4*j + 0].y, o.y);
            o.x = fmaf(q4.y, Sreg[4*j + 1].x, o.x); o.y = fmaf(q4.y, Sreg[4*j + 1].y, o.y);
            o.x = fmaf(q4.z, Sreg[4*j + 2].x, o.x); o.y = fmaf(q4.z, Sreg[4*j + 2].y, o.y);
            o.x = fmaf(q4.w, Sreg[4*j + 3].x, o.x); o.y = fmaf(q4.w, Sreg[4*j + 3].y, o.y);
        }
        *reinterpret_cast<float2*>(y + (size_t)(t0 + tok) * DH + 2 * lane) = o;
    }
}

// ============================================================
extern "C" void kernel_launch(void* const* d_in, const int* in_sizes, int n_in,
                              void* d_out, int out_size) {
    (void)in_sizes; (void)n_in; (void)out_size;
    const float* x  = (const float*)d_in[0];
    const float* w  = (const float*)d_in[1];
    const float* Wq = (const float*)d_in[2];
    const float* bq = (const float*)d_in[3];
    const float* Wk = (const float*)d_in[4];
    const float* bk = (const float*)d_in[5];
    const float* Wv = (const float*)d_in[6];
    const float* bv = (const float*)d_in[7];
    float* y = (float*)d_out;

    static int attr_set = 0;
    if (!attr_set) {
        cudaFuncSetAttribute(phase1_kernel, cudaFuncAttributeMaxDynamicSharedMemorySize, DYN_BYTES);
        attr_set = 1;
    }

    prep_kernel<<<(EMB * NJ + 255) / 256, 256>>>(w, Wq, bq, Wk, bk, Wv, bv);
    phase1_kernel<<<NTILE, 256, DYN_BYTES>>>(x);
    reduce_kernel<<<64, 256>>>();
    phase2_kernel<<<(BATCH * TLEN) / 32, 128>>>(y);
}